// round 5
// baseline (speedup 1.0000x reference)
#include <cuda_runtime.h>
#include <math_constants.h>

#define HH 1024
#define WW 1024
#define CC 128
#define NITER 8
#define TS 32                 // tile side; 1024 tiles total
#define TWO_RHO 43.85f        // 2*sqrt(2)*15.5 (tile half-diagonal), rounded up
#define FULLM 0xFFFFFFFFu
#define NBLK 512              // CTAs; each handles 2 tiles (bid, bid+NBLK)

// 4 rotating cluster position buffers (row,col interleaved)
__device__ float g_pos[4][2 * CC];
// software grid barrier state (persists across replays; targets base-relative)
__device__ unsigned g_bar_count = 0;
__device__ volatile unsigned g_bar_gen = 0;

__device__ __forceinline__ void grid_barrier(unsigned target) {
    __syncthreads();
    if (threadIdx.x == 0) {
        __threadfence();
        unsigned arr = atomicAdd(&g_bar_count, 1u);
        if (arr == NBLK - 1u) {
            atomicExch(&g_bar_count, 0u);     // reset before releasing
            __threadfence();
            atomicAdd((unsigned*)&g_bar_gen, 1u);
        } else {
            while ((int)(g_bar_gen - target) < 0) __nanosleep(32);
            __threadfence();
        }
    }
    __syncthreads();
}

__global__ void __launch_bounds__(256, 4) km_all_kernel(
    const float* __restrict__ clusters,
    const float* __restrict__ heatmap,
    float* __restrict__ out)
{
    __shared__ float2   s_cl[CC];
    __shared__ float2   s_cand[CC];
    __shared__ int      s_cidx[CC];
    __shared__ float    s_acc[2 * CC];
    __shared__ unsigned s_mask[4];
    __shared__ float    s_wmin[8];

    const int t = threadIdx.x;

    // two tiles per CTA: bid and bid+NBLK
    int   trow[2], tcol0[2];
    float tfrow[2], tfc0[2], tcy[2], tcx[2];
    #pragma unroll
    for (int p = 0; p < 2; ++p) {
        const int tile = blockIdx.x + p * NBLK;
        const int tile_c = (tile & 31) * TS;
        const int tile_r = (tile >> 5) * TS;
        trow[p]  = tile_r + (t >> 3);
        tcol0[p] = tile_c + (t & 7) * 4;
        tfrow[p] = (float)trow[p];
        tfc0[p]  = (float)tcol0[p];
        tcy[p]   = (float)tile_r + 15.5f;
        tcx[p]   = (float)tile_c + 15.5f;
    }

    // base generation (monotone across graph replays); read before any bump
    unsigned tgt = g_bar_gen;

    if (blockIdx.x == 0) g_pos[1][t] = 0.0f;   // output buffer of iter 0
    grid_barrier(++tgt);

    #pragma unroll 1
    for (int k = 0; k < NITER; ++k) {
        const float* cin = (k == 0) ? clusters : &g_pos[k & 3][0];
        float* cout = (k == NITER - 1) ? out : &g_pos[(k + 1) & 3][0];

        s_acc[t] = 0.0f;

        // issue both tiles' heatmap loads early (MLP=2; L1-hit after iter 0)
        const float4 h4a = *reinterpret_cast<const float4*>(heatmap + trow[0] * WW + tcol0[0]);
        const float4 h4b = *reinterpret_cast<const float4*>(heatmap + trow[1] * WW + tcol0[1]);

        // cluster positions: load once per iteration (L2; produced by atomics)
        float2 cpos = make_float2(0.f, 0.f);
        if (t < CC) {
            cpos = __ldcg(reinterpret_cast<const float2*>(cin) + t);
            s_cl[t] = cpos;
        }
        __syncthreads();

        // dedup flag once per iteration (tile-independent): a later bitwise-
        // equal cluster can never win strict-< argmin (first index wins)
        bool dup = false;
        if (t < CC) {
            for (int i = 0; i < t; ++i) {
                const float2 ci = s_cl[i];
                if ((ci.x == cpos.x) && (ci.y == cpos.y)) { dup = true; break; }
            }
        }

        #pragma unroll
        for (int p = 0; p < 2; ++p) {
            const float frow = tfrow[p];
            const float fc0 = tfc0[p];
            const float fc1 = fc0 + 1.0f;
            const float fc2 = fc0 + 2.0f;
            const float fc3 = fc0 + 3.0f;
            const float4 h4 = p ? h4b : h4a;

            // ---- Phase A: cull to this tile ----
            float d2c = CUDART_INF_F;
            if (t < CC) {
                const float dr = tcy[p] - cpos.x, dc = tcx[p] - cpos.y;
                d2c = fmaf(dr, dr, dc * dc);
            }
            float m = d2c;
            #pragma unroll
            for (int o = 16; o; o >>= 1) m = fminf(m, __shfl_xor_sync(FULLM, m, o));
            if ((t & 31) == 0) s_wmin[t >> 5] = m;
            __syncthreads();          // also guards s_cand reuse across tiles
            float md2 = s_wmin[0];
            #pragma unroll
            for (int w = 1; w < 8; ++w) md2 = fminf(md2, s_wmin[w]);

            // cluster can win argmin for some pixel in tile only if
            // d(center,c) <= minD + 2*rho; margin keeps fp error conservative
            const float minD = sqrtf(md2);
            const float thr  = minD + TWO_RHO + 4.0f + 1e-5f * minD;
            const float thr2 = thr * thr;

            const bool keep = (t < CC) && (d2c <= thr2) && !dup;
            const unsigned bal = __ballot_sync(FULLM, keep);
            if (((t & 31) == 0) && ((t >> 5) < 4)) s_mask[t >> 5] = bal;
            __syncthreads();
            if (keep) {
                int rank = __popc(bal & ((1u << (t & 31)) - 1u));
                for (int w = 0; w < (t >> 5); ++w) rank += __popc(s_mask[w]);
                s_cand[rank] = cpos;
                s_cidx[rank] = t;
            }
            const int ncand = __popc(s_mask[0]) + __popc(s_mask[1])
                            + __popc(s_mask[2]) + __popc(s_mask[3]);
            __syncthreads();

            // ---- Phase B: per-pixel argmin (candidates in index order) ----
            float b0 = CUDART_INF_F, b1 = CUDART_INF_F, b2 = CUDART_INF_F, b3 = CUDART_INF_F;
            int k0 = 0, k1 = 0, k2 = 0, k3 = 0;

            #pragma unroll 2
            for (int j = 0; j < ncand; ++j) {
                const float2 cl = s_cand[j];
                const float dr = frow - cl.x;
                const float dr2 = dr * dr;
                float dc, d;
                // ordering of max(1,sqrt(d2)) == ordering of max(1,d2)
                dc = fc0 - cl.y; d = fmaxf(fmaf(dc, dc, dr2), 1.0f);
                if (d < b0) { b0 = d; k0 = j; }
                dc = fc1 - cl.y; d = fmaxf(fmaf(dc, dc, dr2), 1.0f);
                if (d < b1) { b1 = d; k1 = j; }
                dc = fc2 - cl.y; d = fmaxf(fmaf(dc, dc, dr2), 1.0f);
                if (d < b2) { b2 = d; k2 = j; }
                dc = fc3 - cl.y; d = fmaxf(fmaf(dc, dc, dr2), 1.0f);
                if (d < b3) { b3 = d; k3 = j; }
            }

            const int i0 = s_cidx[k0];
            const int i1 = s_cidx[k1];
            const int i2 = s_cidx[k2];
            const int i3 = s_cidx[k3];

            // weight = heatmap / max(1, sqrt(d2)) = h * rsqrt(clamped d2)
            const float w0 = h4.x * rsqrtf(b0);
            const float w1 = h4.y * rsqrtf(b1);
            const float w2 = h4.z * rsqrtf(b2);
            const float w3 = h4.w * rsqrtf(b3);

            // ---- scatter: uniform-warp fast path, run-length fallback ----
            const bool uni4 = (i0 == i1) & (i1 == i2) & (i2 == i3);
            const int  u    = __shfl_sync(FULLM, i0, 0);
            const bool alluni = __all_sync(FULLM, uni4 && (i0 == u));

            if (alluni) {
                float rsum = frow * ((w0 + w1) + (w2 + w3));
                float csum = (fc0 * w0 + fc1 * w1) + (fc2 * w2 + fc3 * w3);
                #pragma unroll
                for (int o = 16; o; o >>= 1) {
                    rsum += __shfl_xor_sync(FULLM, rsum, o);
                    csum += __shfl_xor_sync(FULLM, csum, o);
                }
                if ((t & 31) == 0) {
                    atomicAdd(&s_acc[2 * u],     rsum);
                    atomicAdd(&s_acc[2 * u + 1], csum);
                }
            } else {
                int cur = i0;
                float wsum = w0, cwsum = fc0 * w0;
                #define KM_STEP(ii, ww, fcx)                                    \
                    if ((ii) == cur) { wsum += (ww); cwsum += (fcx) * (ww); }   \
                    else {                                                      \
                        atomicAdd(&s_acc[2 * cur],     frow * wsum);            \
                        atomicAdd(&s_acc[2 * cur + 1], cwsum);                  \
                        cur = (ii); wsum = (ww); cwsum = (fcx) * (ww);          \
                    }
                KM_STEP(i1, w1, fc1)
                KM_STEP(i2, w2, fc2)
                KM_STEP(i3, w3, fc3)
                #undef KM_STEP
                atomicAdd(&s_acc[2 * cur],     frow * wsum);
                atomicAdd(&s_acc[2 * cur + 1], cwsum);
            }
        }

        __syncthreads();
        // global accumulate once per CTA (both tiles merged); skip zeros
        const float v = s_acc[t];
        if (v != 0.0f) atomicAdd(&cout[t], v);

        // block 0 zeroes the output buffer of iteration k+2 (idle this iter)
        if (blockIdx.x == 0) {
            if (k == NITER - 2)      { /* nothing left */ }
            else if (k == NITER - 3) out[t] = 0.0f;            // iter 7 -> d_out
            else                     g_pos[(k + 2) & 3][t] = 0.0f;
        }

        if (k < NITER - 1) grid_barrier(++tgt);
    }
}

extern "C" void kernel_launch(void* const* d_in, const int* in_sizes, int n_in,
                              void* d_out, int out_size) {
    const float* clusters = (const float*)d_in[0];
    const float* heatmap  = (const float*)d_in[1];
    if (n_in >= 2 && in_sizes[0] != 2 * CC) {
        const float* tmp = clusters; clusters = heatmap; heatmap = tmp;
    }
    km_all_kernel<<<NBLK, 256>>>(clusters, heatmap, (float*)d_out);
}

// round 6
// speedup vs baseline: 1.3215x; 1.3215x over previous
#include <cuda_runtime.h>
#include <math_constants.h>

#define HH 1024
#define WW 1024
#define CC 128
#define NITER 8
#define TS 32                 // tile side; grid = 1024 tiles, 1 per CTA
#define TWO_RHO 43.85f        // 2*sqrt(2)*15.5 (tile half-diagonal), rounded up
#define FULLM 0xFFFFFFFFu
#define NBLK 1024

// 4 rotating cluster position buffers (row,col interleaved)
__device__ float g_pos[4][2 * CC];
// software grid barrier state (persists across replays; targets base-relative)
__device__ unsigned g_bar_count = 0;
__device__ volatile unsigned g_bar_gen = 0;

__device__ __forceinline__ void grid_barrier(unsigned target) {
    __syncthreads();
    if (threadIdx.x == 0) {
        __threadfence();
        unsigned arr = atomicAdd(&g_bar_count, 1u);
        if (arr == NBLK - 1u) {
            atomicExch(&g_bar_count, 0u);     // reset before releasing
            __threadfence();
            atomicAdd((unsigned*)&g_bar_gen, 1u);
        } else {
            while ((int)(g_bar_gen - target) < 0) __nanosleep(32);
            __threadfence();
        }
    }
    __syncthreads();
}

// warp-wide min of a uint in one instruction (nonneg float bits are
// order-isomorphic to their uint encoding)
__device__ __forceinline__ unsigned warp_min_u32(unsigned v) {
    unsigned r;
    asm volatile("redux.sync.min.u32 %0, %1, 0xffffffff;" : "=r"(r) : "r"(v));
    return r;
}

__global__ void __launch_bounds__(256, 7) km_all_kernel(
    const float* __restrict__ clusters,
    const float* __restrict__ heatmap,
    float* __restrict__ out)
{
    __shared__ float2   s_cand[CC];
    __shared__ int      s_cidx[CC];
    __shared__ float    s_acc[2 * CC];
    __shared__ unsigned s_mask[8];
    __shared__ unsigned s_wmin[8];
    __shared__ unsigned s_zmask[8];

    const int t = threadIdx.x;
    const int wid = t >> 5;
    const int tile_c = (blockIdx.x & 31) * TS;
    const int tile_r = (blockIdx.x >> 5) * TS;
    const int row  = tile_r + (t >> 3);
    const int col0 = tile_c + (t & 7) * 4;
    const float frow = (float)row;
    const float fc0 = (float)col0;
    const float fc1 = fc0 + 1.0f;
    const float fc2 = fc0 + 2.0f;
    const float fc3 = fc0 + 3.0f;
    const float cy = (float)tile_r + 15.5f;
    const float cx = (float)tile_c + 15.5f;

    // heatmap values for this thread's 4 pixels: constant across iterations
    const float4 h4 = *reinterpret_cast<const float4*>(heatmap + row * WW + col0);

    // base generation (monotone across graph replays); read before any bump
    unsigned tgt = g_bar_gen;

    if (blockIdx.x == 0) g_pos[1][t] = 0.0f;   // output buffer of iter 0
    grid_barrier(++tgt);

    #pragma unroll 1
    for (int k = 0; k < NITER; ++k) {
        const float* cin = (k == 0) ? clusters : &g_pos[k & 3][0];
        float* cout = (k == NITER - 1) ? out : &g_pos[(k + 1) & 3][0];

        s_acc[t] = 0.0f;

        // ---- Phase A: per-tile cull + O(1) zero-dup removal ----
        float d2c = CUDART_INF_F;
        float2 cpos = make_float2(0.f, 0.f);
        bool iszero = false;
        if (t < CC) {
            // L2 load: positions were produced by global atomics on other SMs
            cpos = __ldcg(reinterpret_cast<const float2*>(cin) + t);
            iszero = (cpos.x == 0.0f) && (cpos.y == 0.0f);
            const float dr = cy - cpos.x, dc = cx - cpos.y;
            d2c = fmaf(dr, dr, dc * dc);
        }
        const unsigned zb = __ballot_sync(FULLM, iszero);
        const unsigned mb = warp_min_u32(__float_as_uint(d2c));
        if ((t & 31) == 0) { s_wmin[wid] = mb; s_zmask[wid] = zb; }
        __syncthreads();

        unsigned mdu = s_wmin[0];
        #pragma unroll
        for (int w = 1; w < 4; ++w) mdu = min(mdu, s_wmin[w]);
        const float md2 = __uint_as_float(mdu);

        // first exactly-(0,0) cluster index (empty clusters collapse to 0);
        // later (0,0) duplicates can never win strict-< argmin -> drop them.
        // Other bitwise dups are rare and harmless (strict < keeps first).
        int firstZero = 256;
        #pragma unroll
        for (int w = 3; w >= 0; --w)
            if (s_zmask[w]) firstZero = w * 32 + (__ffs(s_zmask[w]) - 1);

        // cluster can win argmin for some pixel in tile only if
        // d(center,c) <= minD + 2*rho; margin keeps fp error conservative
        const float minD = sqrtf(md2);
        const float thr  = minD + TWO_RHO + 4.0f + 1e-5f * minD;
        const float thr2 = thr * thr;

        const bool keep = (t < CC) && (d2c <= thr2) && !(iszero && t != firstZero);
        const unsigned bal = __ballot_sync(FULLM, keep);
        if ((t & 31) == 0) s_mask[wid] = bal;
        __syncthreads();
        if (keep) {
            int rank = __popc(bal & ((1u << (t & 31)) - 1u));
            for (int w = 0; w < wid; ++w) rank += __popc(s_mask[w]);
            s_cand[rank] = cpos;
            s_cidx[rank] = t;
        }
        const int ncand = __popc(s_mask[0]) + __popc(s_mask[1])
                        + __popc(s_mask[2]) + __popc(s_mask[3]);
        __syncthreads();

        // ---- Phase B: per-pixel argmin (candidates in index order) ----
        float b0 = CUDART_INF_F, b1 = CUDART_INF_F, b2 = CUDART_INF_F, b3 = CUDART_INF_F;
        int k0 = 0, k1 = 0, k2 = 0, k3 = 0;

        #pragma unroll 2
        for (int j = 0; j < ncand; ++j) {
            const float2 cl = s_cand[j];
            const float dr = frow - cl.x;
            const float dr2 = dr * dr;
            float dc, d;
            // ordering of max(1,sqrt(d2)) == ordering of max(1,d2); strict <
            dc = fc0 - cl.y; d = fmaxf(fmaf(dc, dc, dr2), 1.0f);
            if (d < b0) { b0 = d; k0 = j; }
            dc = fc1 - cl.y; d = fmaxf(fmaf(dc, dc, dr2), 1.0f);
            if (d < b1) { b1 = d; k1 = j; }
            dc = fc2 - cl.y; d = fmaxf(fmaf(dc, dc, dr2), 1.0f);
            if (d < b2) { b2 = d; k2 = j; }
            dc = fc3 - cl.y; d = fmaxf(fmaf(dc, dc, dr2), 1.0f);
            if (d < b3) { b3 = d; k3 = j; }
        }

        const int i0 = s_cidx[k0];
        const int i1 = s_cidx[k1];
        const int i2 = s_cidx[k2];
        const int i3 = s_cidx[k3];

        // weight = heatmap / max(1, sqrt(d2)) = h * rsqrt(clamped d2)
        const float w0 = h4.x * rsqrtf(b0);
        const float w1 = h4.y * rsqrtf(b1);
        const float w2 = h4.z * rsqrtf(b2);
        const float w3 = h4.w * rsqrtf(b3);

        // ---- scatter: uniform-warp fast path, run-length fallback ----
        const bool uni4 = (i0 == i1) & (i1 == i2) & (i2 == i3);
        const int  u    = __shfl_sync(FULLM, i0, 0);
        const bool alluni = __all_sync(FULLM, uni4 && (i0 == u));

        if (alluni) {
            float rsum = frow * ((w0 + w1) + (w2 + w3));
            float csum = (fc0 * w0 + fc1 * w1) + (fc2 * w2 + fc3 * w3);
            #pragma unroll
            for (int o = 16; o; o >>= 1) {
                rsum += __shfl_xor_sync(FULLM, rsum, o);
                csum += __shfl_xor_sync(FULLM, csum, o);
            }
            if ((t & 31) == 0) {
                atomicAdd(&s_acc[2 * u],     rsum);
                atomicAdd(&s_acc[2 * u + 1], csum);
            }
        } else {
            int cur = i0;
            float wsum = w0, cwsum = fc0 * w0;
            #define KM_STEP(ii, ww, fcx)                                    \
                if ((ii) == cur) { wsum += (ww); cwsum += (fcx) * (ww); }   \
                else {                                                      \
                    atomicAdd(&s_acc[2 * cur],     frow * wsum);            \
                    atomicAdd(&s_acc[2 * cur + 1], cwsum);                  \
                    cur = (ii); wsum = (ww); cwsum = (fcx) * (ww);          \
                }
            KM_STEP(i1, w1, fc1)
            KM_STEP(i2, w2, fc2)
            KM_STEP(i3, w3, fc3)
            #undef KM_STEP
            atomicAdd(&s_acc[2 * cur],     frow * wsum);
            atomicAdd(&s_acc[2 * cur + 1], cwsum);
        }

        __syncthreads();
        // global accumulate; skip zeros (all contributions are >= +0)
        const float v = s_acc[t];
        if (v != 0.0f) atomicAdd(&cout[t], v);

        // block 0 zeroes the output buffer of iteration k+2 (idle this iter)
        if (blockIdx.x == 0) {
            if (k == NITER - 2)      { /* nothing left */ }
            else if (k == NITER - 3) out[t] = 0.0f;            // iter 7 -> d_out
            else                     g_pos[(k + 2) & 3][t] = 0.0f;
        }

        if (k < NITER - 1) grid_barrier(++tgt);
    }
}

extern "C" void kernel_launch(void* const* d_in, const int* in_sizes, int n_in,
                              void* d_out, int out_size) {
    const float* clusters = (const float*)d_in[0];
    const float* heatmap  = (const float*)d_in[1];
    if (n_in >= 2 && in_sizes[0] != 2 * CC) {
        const float* tmp = clusters; clusters = heatmap; heatmap = tmp;
    }
    km_all_kernel<<<NBLK, 256>>>(clusters, heatmap, (float*)d_out);
}

// round 7
// speedup vs baseline: 1.4769x; 1.1176x over previous
#include <cuda_runtime.h>
#include <math_constants.h>

#define HH 1024
#define WW 1024
#define CC 128
#define NITER 8
#define TS 32                 // tile side; grid = 1024 tiles, 1 per CTA
#define TWO_RHO 43.85f        // 2*sqrt(2)*15.5 (tile half-diagonal), rounded up
#define FULLM 0xFFFFFFFFu
#define NBLK 1024

// 4 rotating cluster position buffers (row,col interleaved).
// Invariant: g_pos[1] is all-zero at kernel entry (static init covers the
// first run; block 0 re-zeroes it at k==6 each run for the next replay).
__device__ float g_pos[4][2 * CC];
// software grid barrier: counter and generation on SEPARATE 128B lines
__device__ __align__(128) unsigned g_cnt[32];
__device__ __align__(128) unsigned g_gen[32];

__device__ __forceinline__ unsigned ld_acquire_gpu(const unsigned* p) {
    unsigned v;
    asm volatile("ld.acquire.gpu.u32 %0, [%1];" : "=r"(v) : "l"(p) : "memory");
    return v;
}

// All cross-CTA data traffic is L2-native (global atomics + __ldcg), so
// scoped release/acquire atomics give full ordering with no membar/CCTL.
__device__ __forceinline__ void grid_barrier(unsigned target) {
    __syncthreads();
    if (threadIdx.x == 0) {
        unsigned old;
        // acq_rel: releases this CTA's prior writes/atomics and (for the last
        // arriver) acquires every earlier CTA's release through the RMW chain
        asm volatile("atom.add.acq_rel.gpu.u32 %0, [%1], %2;"
                     : "=r"(old) : "l"(&g_cnt[0]), "r"(1u) : "memory");
        if (old == NBLK - 1u) {
            // reset before release; release-bump publishes reset + all work
            asm volatile("st.relaxed.gpu.u32 [%0], %1;"
                         :: "l"(&g_cnt[0]), "r"(0u) : "memory");
            asm volatile("red.add.release.gpu.u32 [%0], %1;"
                         :: "l"(&g_gen[0]), "r"(1u) : "memory");
        } else {
            unsigned g;
            do {
                __nanosleep(32);
                g = ld_acquire_gpu(&g_gen[0]);
            } while ((int)(g - target) < 0);
        }
    }
    __syncthreads();
}

// warp-wide min of a uint (nonneg float bits are order-isomorphic)
__device__ __forceinline__ unsigned warp_min_u32(unsigned v) {
    unsigned r;
    asm volatile("redux.sync.min.u32 %0, %1, 0xffffffff;" : "=r"(r) : "r"(v));
    return r;
}

__global__ void __launch_bounds__(256, 7) km_all_kernel(
    const float* __restrict__ clusters,
    const float* __restrict__ heatmap,
    float* __restrict__ out)
{
    __shared__ float2   s_cand[CC];
    __shared__ int      s_cidx[CC];
    __shared__ float    s_acc[2 * CC];
    __shared__ unsigned s_mask[8];
    __shared__ unsigned s_wmin[8];
    __shared__ unsigned s_zmask[8];

    const int t = threadIdx.x;
    const int wid = t >> 5;
    const int tile_c = (blockIdx.x & 31) * TS;
    const int tile_r = (blockIdx.x >> 5) * TS;
    const int row  = tile_r + (t >> 3);
    const int col0 = tile_c + (t & 7) * 4;
    const float frow = (float)row;
    const float fc0 = (float)col0;
    const float fc1 = fc0 + 1.0f;
    const float fc2 = fc0 + 2.0f;
    const float fc3 = fc0 + 3.0f;
    const float cy = (float)tile_r + 15.5f;
    const float cx = (float)tile_c + 15.5f;

    // heatmap values for this thread's 4 pixels: constant across iterations
    const float4 h4 = *reinterpret_cast<const float4*>(heatmap + row * WW + col0);

    // base generation (monotone across replays); every CTA reads it before any
    // bump can occur (a bump needs all NBLK arrivals, each preceded by a read)
    unsigned tgt = ld_acquire_gpu(&g_gen[0]);

    #pragma unroll 1
    for (int k = 0; k < NITER; ++k) {
        const float* cin = (k == 0) ? clusters : &g_pos[k & 3][0];
        float* cout = (k == NITER - 1) ? out : &g_pos[(k + 1) & 3][0];

        s_acc[t] = 0.0f;

        // ---- Phase A: per-tile cull + O(1) zero-dup removal ----
        float d2c = CUDART_INF_F;
        float2 cpos = make_float2(0.f, 0.f);
        bool iszero = false;
        if (t < CC) {
            // L2 load: positions were produced by global atomics on other SMs
            cpos = __ldcg(reinterpret_cast<const float2*>(cin) + t);
            iszero = (cpos.x == 0.0f) && (cpos.y == 0.0f);
            const float dr = cy - cpos.x, dc = cx - cpos.y;
            d2c = fmaf(dr, dr, dc * dc);
        }
        const unsigned zb = __ballot_sync(FULLM, iszero);
        const unsigned mb = warp_min_u32(__float_as_uint(d2c));
        if ((t & 31) == 0) { s_wmin[wid] = mb; s_zmask[wid] = zb; }
        __syncthreads();

        unsigned mdu = s_wmin[0];
        #pragma unroll
        for (int w = 1; w < 4; ++w) mdu = min(mdu, s_wmin[w]);
        const float md2 = __uint_as_float(mdu);

        // first exactly-(0,0) cluster index (empty clusters collapse to 0);
        // later (0,0) duplicates can never win strict-< argmin -> drop them.
        // Other bitwise dups are rare and harmless (strict < keeps first).
        int firstZero = 256;
        #pragma unroll
        for (int w = 3; w >= 0; --w)
            if (s_zmask[w]) firstZero = w * 32 + (__ffs(s_zmask[w]) - 1);

        // cluster can win argmin for some pixel in tile only if
        // d(center,c) <= minD + 2*rho; margin keeps fp error conservative
        const float minD = sqrtf(md2);
        const float thr  = minD + TWO_RHO + 4.0f + 1e-5f * minD;
        const float thr2 = thr * thr;

        const bool keep = (t < CC) && (d2c <= thr2) && !(iszero && t != firstZero);
        const unsigned bal = __ballot_sync(FULLM, keep);
        if ((t & 31) == 0) s_mask[wid] = bal;
        __syncthreads();
        if (keep) {
            int rank = __popc(bal & ((1u << (t & 31)) - 1u));
            for (int w = 0; w < wid; ++w) rank += __popc(s_mask[w]);
            s_cand[rank] = cpos;
            s_cidx[rank] = t;
        }
        const int ncand = __popc(s_mask[0]) + __popc(s_mask[1])
                        + __popc(s_mask[2]) + __popc(s_mask[3]);
        __syncthreads();

        // ---- Phase B: per-pixel argmin (candidates in index order) ----
        float b0 = CUDART_INF_F, b1 = CUDART_INF_F, b2 = CUDART_INF_F, b3 = CUDART_INF_F;
        int k0 = 0, k1 = 0, k2 = 0, k3 = 0;

        #pragma unroll 2
        for (int j = 0; j < ncand; ++j) {
            const float2 cl = s_cand[j];
            const float dr = frow - cl.x;
            const float dr2 = dr * dr;
            float dc, d;
            // ordering of max(1,sqrt(d2)) == ordering of max(1,d2); strict <
            dc = fc0 - cl.y; d = fmaxf(fmaf(dc, dc, dr2), 1.0f);
            if (d < b0) { b0 = d; k0 = j; }
            dc = fc1 - cl.y; d = fmaxf(fmaf(dc, dc, dr2), 1.0f);
            if (d < b1) { b1 = d; k1 = j; }
            dc = fc2 - cl.y; d = fmaxf(fmaf(dc, dc, dr2), 1.0f);
            if (d < b2) { b2 = d; k2 = j; }
            dc = fc3 - cl.y; d = fmaxf(fmaf(dc, dc, dr2), 1.0f);
            if (d < b3) { b3 = d; k3 = j; }
        }

        const int i0 = s_cidx[k0];
        const int i1 = s_cidx[k1];
        const int i2 = s_cidx[k2];
        const int i3 = s_cidx[k3];

        // weight = heatmap / max(1, sqrt(d2)) = h * rsqrt(clamped d2)
        const float w0 = h4.x * rsqrtf(b0);
        const float w1 = h4.y * rsqrtf(b1);
        const float w2 = h4.z * rsqrtf(b2);
        const float w3 = h4.w * rsqrtf(b3);

        // ---- scatter: uniform-warp fast path, run-length fallback ----
        const bool uni4 = (i0 == i1) & (i1 == i2) & (i2 == i3);
        const int  u    = __shfl_sync(FULLM, i0, 0);
        const bool alluni = __all_sync(FULLM, uni4 && (i0 == u));

        if (alluni) {
            float rsum = frow * ((w0 + w1) + (w2 + w3));
            float csum = (fc0 * w0 + fc1 * w1) + (fc2 * w2 + fc3 * w3);
            #pragma unroll
            for (int o = 16; o; o >>= 1) {
                rsum += __shfl_xor_sync(FULLM, rsum, o);
                csum += __shfl_xor_sync(FULLM, csum, o);
            }
            if ((t & 31) == 0) {
                atomicAdd(&s_acc[2 * u],     rsum);
                atomicAdd(&s_acc[2 * u + 1], csum);
            }
        } else {
            int cur = i0;
            float wsum = w0, cwsum = fc0 * w0;
            #define KM_STEP(ii, ww, fcx)                                    \
                if ((ii) == cur) { wsum += (ww); cwsum += (fcx) * (ww); }   \
                else {                                                      \
                    atomicAdd(&s_acc[2 * cur],     frow * wsum);            \
                    atomicAdd(&s_acc[2 * cur + 1], cwsum);                  \
                    cur = (ii); wsum = (ww); cwsum = (fcx) * (ww);          \
                }
            KM_STEP(i1, w1, fc1)
            KM_STEP(i2, w2, fc2)
            KM_STEP(i3, w3, fc3)
            #undef KM_STEP
            atomicAdd(&s_acc[2 * cur],     frow * wsum);
            atomicAdd(&s_acc[2 * cur + 1], cwsum);
        }

        __syncthreads();
        // global accumulate; skip zeros (all contributions are >= +0)
        const float v = s_acc[t];
        if (v != 0.0f) atomicAdd(&cout[t], v);

        // block 0 zeroes a buffer that is idle this iteration:
        //  k<=4 : output buffer of iteration k+2
        //  k==5 : d_out (output of iteration 7)
        //  k==6 : g_pos[1] (restores entry invariant for the next replay)
        if (blockIdx.x == 0) {
            if (k <= 4)      g_pos[(k + 2) & 3][t] = 0.0f;
            else if (k == 5) out[t] = 0.0f;
            else if (k == 6) g_pos[1][t] = 0.0f;
        }

        if (k < NITER - 1) grid_barrier(++tgt);
    }
}

extern "C" void kernel_launch(void* const* d_in, const int* in_sizes, int n_in,
                              void* d_out, int out_size) {
    const float* clusters = (const float*)d_in[0];
    const float* heatmap  = (const float*)d_in[1];
    if (n_in >= 2 && in_sizes[0] != 2 * CC) {
        const float* tmp = clusters; clusters = heatmap; heatmap = tmp;
    }
    km_all_kernel<<<NBLK, 256>>>(clusters, heatmap, (float*)d_out);
}

// round 8
// speedup vs baseline: 1.6491x; 1.1165x over previous
#include <cuda_runtime.h>
#include <math_constants.h>

#define HH 1024
#define WW 1024
#define CC 128
#define NITER 8
#define TWO_RHO 71.6f         // 2 * sqrt(16^2 + 32^2) for a 32x64 region
#define FULLM 0xFFFFFFFFu
#define NBLK 512              // one CTA per 32-row x 64-col region

// 4 rotating cluster position buffers (row,col interleaved).
// Invariant: g_pos[1] is all-zero at kernel entry (static init covers the
// first run; block 0 re-zeroes it at k==6 each run for the next replay).
__device__ float g_pos[4][2 * CC];
// software grid barrier: counter and generation on SEPARATE 128B lines
__device__ __align__(128) unsigned g_cnt[32];
__device__ __align__(128) unsigned g_gen[32];

__device__ __forceinline__ unsigned ld_acquire_gpu(const unsigned* p) {
    unsigned v;
    asm volatile("ld.acquire.gpu.u32 %0, [%1];" : "=r"(v) : "l"(p) : "memory");
    return v;
}

// All cross-CTA data traffic is L2-native (global atomics + __ldcg), so
// scoped release/acquire atomics give full ordering with no membar/CCTL.
__device__ __forceinline__ void grid_barrier(unsigned target) {
    __syncthreads();
    if (threadIdx.x == 0) {
        unsigned old;
        asm volatile("atom.add.acq_rel.gpu.u32 %0, [%1], %2;"
                     : "=r"(old) : "l"(&g_cnt[0]), "r"(1u) : "memory");
        if (old == NBLK - 1u) {
            asm volatile("st.relaxed.gpu.u32 [%0], %1;"
                         :: "l"(&g_cnt[0]), "r"(0u) : "memory");
            asm volatile("red.add.release.gpu.u32 [%0], %1;"
                         :: "l"(&g_gen[0]), "r"(1u) : "memory");
        } else {
            unsigned g = ld_acquire_gpu(&g_gen[0]);
            int spins = 0;
            while ((int)(g - target) < 0) {
                if (++spins > 4) __nanosleep(40);   // hot-spin first, then doze
                g = ld_acquire_gpu(&g_gen[0]);
            }
        }
    }
    __syncthreads();
}

// warp-wide min of a uint (nonneg float bits are order-isomorphic)
__device__ __forceinline__ unsigned warp_min_u32(unsigned v) {
    unsigned r;
    asm volatile("redux.sync.min.u32 %0, %1, 0xffffffff;" : "=r"(r) : "r"(v));
    return r;
}

__global__ void __launch_bounds__(256, 4) km_all_kernel(
    const float* __restrict__ clusters,
    const float* __restrict__ heatmap,
    float* __restrict__ out)
{
    __shared__ float2   s_cand[CC];
    __shared__ int      s_cidx[CC];
    __shared__ float    s_acc[2 * CC];
    __shared__ unsigned s_mask[8];
    __shared__ unsigned s_wmin[8];
    __shared__ unsigned s_zmask[8];

    const int t = threadIdx.x;
    const int wid = t >> 5;
    // 32-row x 64-col region per CTA; 8 consecutive pixels per thread
    const int region_c = (blockIdx.x & 15) * 64;
    const int region_r = (blockIdx.x >> 4) * 32;
    const int row  = region_r + (t >> 3);
    const int col0 = region_c + (t & 7) * 8;
    const float frow = (float)row;
    const float fc0  = (float)col0;
    const float cy = (float)region_r + 15.5f;
    const float cx = (float)region_c + 31.5f;

    // heatmap values for this thread's 8 pixels: constant across iterations
    float h[8];
    {
        const float4 a = *reinterpret_cast<const float4*>(heatmap + row * WW + col0);
        const float4 b = *reinterpret_cast<const float4*>(heatmap + row * WW + col0 + 4);
        h[0] = a.x; h[1] = a.y; h[2] = a.z; h[3] = a.w;
        h[4] = b.x; h[5] = b.y; h[6] = b.z; h[7] = b.w;
    }

    // base generation (monotone across replays); every CTA reads it before any
    // bump can occur (a bump needs all NBLK arrivals, each preceded by a read)
    unsigned tgt = ld_acquire_gpu(&g_gen[0]);

    #pragma unroll 1
    for (int k = 0; k < NITER; ++k) {
        const float* cin = (k == 0) ? clusters : &g_pos[k & 3][0];
        float* cout = (k == NITER - 1) ? out : &g_pos[(k + 1) & 3][0];

        s_acc[t] = 0.0f;

        // ---- Phase A: per-region cull + O(1) zero-dup removal ----
        float d2c = CUDART_INF_F;
        float2 cpos = make_float2(0.f, 0.f);
        bool iszero = false;
        if (t < CC) {
            // L2 load: positions were produced by global atomics on other SMs
            cpos = __ldcg(reinterpret_cast<const float2*>(cin) + t);
            iszero = (cpos.x == 0.0f) && (cpos.y == 0.0f);
            const float dr = cy - cpos.x, dc = cx - cpos.y;
            d2c = fmaf(dr, dr, dc * dc);
        }
        const unsigned zb = __ballot_sync(FULLM, iszero);
        const unsigned mb = warp_min_u32(__float_as_uint(d2c));
        if ((t & 31) == 0) { s_wmin[wid] = mb; s_zmask[wid] = zb; }
        __syncthreads();

        unsigned mdu = s_wmin[0];
        #pragma unroll
        for (int w = 1; w < 4; ++w) mdu = min(mdu, s_wmin[w]);
        const float md2 = __uint_as_float(mdu);

        // first exactly-(0,0) cluster index (empty clusters collapse to 0);
        // later (0,0) duplicates can never win strict-< argmin -> drop them.
        // Other bitwise dups are rare and harmless (strict < keeps first).
        int firstZero = 256;
        #pragma unroll
        for (int w = 3; w >= 0; --w)
            if (s_zmask[w]) firstZero = w * 32 + (__ffs(s_zmask[w]) - 1);

        // cluster can win argmin for some pixel in region only if
        // d(center,c) <= minD + 2*rho; margin keeps fp error conservative
        const float minD = sqrtf(md2);
        const float thr  = minD + TWO_RHO + 4.0f + 1e-5f * minD;
        const float thr2 = thr * thr;

        const bool keep = (t < CC) && (d2c <= thr2) && !(iszero && t != firstZero);
        const unsigned bal = __ballot_sync(FULLM, keep);
        if ((t & 31) == 0) s_mask[wid] = bal;
        __syncthreads();
        if (keep) {
            int rank = __popc(bal & ((1u << (t & 31)) - 1u));
            for (int w = 0; w < wid; ++w) rank += __popc(s_mask[w]);
            s_cand[rank] = cpos;
            s_cidx[rank] = t;
        }
        const int ncand = __popc(s_mask[0]) + __popc(s_mask[1])
                        + __popc(s_mask[2]) + __popc(s_mask[3]);
        __syncthreads();

        // ---- Phase B: 8-pixel argmin (candidates in index order) ----
        float b[8];
        int   kk[8];
        #pragma unroll
        for (int q = 0; q < 8; ++q) { b[q] = CUDART_INF_F; kk[q] = 0; }

        #pragma unroll 2
        for (int j = 0; j < ncand; ++j) {
            const float2 cl = s_cand[j];
            const float dr = frow - cl.x;
            const float dr2 = dr * dr;
            #pragma unroll
            for (int q = 0; q < 8; ++q) {
                // ordering of max(1,sqrt(d2)) == ordering of max(1,d2)
                const float dc = (fc0 + (float)q) - cl.y;
                const float d = fmaxf(fmaf(dc, dc, dr2), 1.0f);
                if (d < b[q]) { b[q] = d; kk[q] = j; }
            }
        }

        int idx[8];
        float w8[8];
        #pragma unroll
        for (int q = 0; q < 8; ++q) {
            idx[q] = s_cidx[kk[q]];
            // weight = heatmap / max(1,sqrt(d2)) = h * rsqrt(clamped d2)
            w8[q] = h[q] * rsqrtf(b[q]);
        }

        // ---- scatter: uniform-warp fast path, run-length fallback ----
        bool uni = true;
        #pragma unroll
        for (int q = 1; q < 8; ++q) uni = uni && (idx[q] == idx[0]);
        const int  u      = __shfl_sync(FULLM, idx[0], 0);
        const bool alluni = __all_sync(FULLM, uni && (idx[0] == u));

        if (alluni) {
            float wsum = ((w8[0] + w8[1]) + (w8[2] + w8[3]))
                       + ((w8[4] + w8[5]) + (w8[6] + w8[7]));
            float csum = 0.0f;
            #pragma unroll
            for (int q = 0; q < 8; ++q) csum = fmaf(fc0 + (float)q, w8[q], csum);
            float rsum = frow * wsum;
            #pragma unroll
            for (int o = 16; o; o >>= 1) {
                rsum += __shfl_xor_sync(FULLM, rsum, o);
                csum += __shfl_xor_sync(FULLM, csum, o);
            }
            if ((t & 31) == 0) {
                atomicAdd(&s_acc[2 * u],     rsum);
                atomicAdd(&s_acc[2 * u + 1], csum);
            }
        } else {
            int cur = idx[0];
            float wsum = w8[0], cwsum = fc0 * w8[0];
            #pragma unroll
            for (int q = 1; q < 8; ++q) {
                const float fcq = fc0 + (float)q;
                if (idx[q] == cur) { wsum += w8[q]; cwsum = fmaf(fcq, w8[q], cwsum); }
                else {
                    atomicAdd(&s_acc[2 * cur],     frow * wsum);
                    atomicAdd(&s_acc[2 * cur + 1], cwsum);
                    cur = idx[q]; wsum = w8[q]; cwsum = fcq * w8[q];
                }
            }
            atomicAdd(&s_acc[2 * cur],     frow * wsum);
            atomicAdd(&s_acc[2 * cur + 1], cwsum);
        }

        __syncthreads();
        // global accumulate; skip zeros (all contributions are >= +0)
        const float v = s_acc[t];
        if (v != 0.0f) atomicAdd(&cout[t], v);

        // block 0 zeroes a buffer that is idle this iteration:
        //  k<=4 : output buffer of iteration k+2
        //  k==5 : d_out (output of iteration 7)
        //  k==6 : g_pos[1] (restores entry invariant for the next replay)
        if (blockIdx.x == 0) {
            if (k <= 4)      g_pos[(k + 2) & 3][t] = 0.0f;
            else if (k == 5) out[t] = 0.0f;
            else if (k == 6) g_pos[1][t] = 0.0f;
        }

        if (k < NITER - 1) grid_barrier(++tgt);
    }
}

extern "C" void kernel_launch(void* const* d_in, const int* in_sizes, int n_in,
                              void* d_out, int out_size) {
    const float* clusters = (const float*)d_in[0];
    const float* heatmap  = (const float*)d_in[1];
    if (n_in >= 2 && in_sizes[0] != 2 * CC) {
        const float* tmp = clusters; clusters = heatmap; heatmap = tmp;
    }
    km_all_kernel<<<NBLK, 256>>>(clusters, heatmap, (float*)d_out);
}